// round 13
// baseline (speedup 1.0000x reference)
#include <cuda_runtime.h>
#include <cuda_bf16.h>

// Problem constants
#define TT   4096
#define HH   16
#define DKK  128
#define QKVC 6144
#define NELEM (TT * HH * DKK)   // 8388608

// Scratch (static __device__ globals — no runtime allocation)
// g_P packed per (t,h): [slot0(128) | a(128) | k(128) | q(128)]
// slot0 holds ka after prep; pass2 overwrites it in place with
// w_t = ka_t ∘ a_{t-1} ∘ a_{t-2} (only warp (t,h) ever touches slot0 of (t,h)).
__device__ __align__(16) float g_P [TT * HH * 512];
__device__ __align__(16) float g_BV[NELEM];        // b * (conv+silu v)
__device__ __align__(16) float g_S4[TT * HH * 4];  // {b, R, Q, 0} per (t,h)
__device__ float g_B[TT * HH];                     // sigmoid(beta)

typedef unsigned long long ull;

// --------------------------------------------------------------------------
// f32x2 packed-math helpers (FFMA2 path; ptxas only emits via PTX f32x2)
// --------------------------------------------------------------------------
__device__ __forceinline__ ull ffma2(ull a, ull b, ull c) {
    ull d;
    asm("fma.rn.f32x2 %0, %1, %2, %3;" : "=l"(d) : "l"(a), "l"(b), "l"(c));
    return d;
}
__device__ __forceinline__ ull fmul2(ull a, ull b) {
    ull d;
    asm("mul.rn.f32x2 %0, %1, %2;" : "=l"(d) : "l"(a), "l"(b));
    return d;
}
__device__ __forceinline__ float hsum2(ull a) {
    float lo, hi;
    asm("mov.b64 {%0, %1}, %2;" : "=f"(lo), "=f"(hi) : "l"(a));
    return lo + hi;
}
__device__ __forceinline__ ull pack2(float x) {
    ull d;
    asm("mov.b64 %0, {%1, %1};" : "=l"(d) : "f"(x));
    return d;
}

// cp.async helper
__device__ __forceinline__ void cp16(float* dst, const float* src) {
    unsigned d = (unsigned)__cvta_generic_to_shared(dst);
    asm volatile("cp.async.cg.shared.global [%0], [%1], 16;"
                 :: "r"(d), "l"(src) : "memory");
}

// --------------------------------------------------------------------------
// Kernel 1: conv1d(K=4, depthwise, causal) + SiLU + l2norm + gate precompute
// One warp per (t, h); lane handles 4 consecutive d via float4.  (R8 version)
// --------------------------------------------------------------------------
__device__ __forceinline__ void conv_silu4(const float* __restrict__ x,
                                           const float* __restrict__ w,
                                           int t, int c, float out[4]) {
    float wz[4][4];
#pragma unroll
    for (int j = 0; j < 4; j++) {
        float4 wv = *(const float4*)(w + (size_t)(c + j) * 4);
        wz[j][0] = wv.x; wz[j][1] = wv.y; wz[j][2] = wv.z; wz[j][3] = wv.w;
    }
    float acc[4] = {0.f, 0.f, 0.f, 0.f};
#pragma unroll
    for (int tau = 0; tau < 4; tau++) {
        int tt = t - 3 + tau;
        if (tt >= 0) {
            float4 xv = *(const float4*)(x + (size_t)tt * QKVC + c);
            acc[0] = fmaf(xv.x, wz[0][tau], acc[0]);
            acc[1] = fmaf(xv.y, wz[1][tau], acc[1]);
            acc[2] = fmaf(xv.z, wz[2][tau], acc[2]);
            acc[3] = fmaf(xv.w, wz[3][tau], acc[3]);
        }
    }
#pragma unroll
    for (int j = 0; j < 4; j++)
        out[j] = acc[j] / (1.f + expf(-acc[j]));   // SiLU
}

__global__ void prep_kernel(const float* __restrict__ qkv,
                            const float* __restrict__ fg,
                            const float* __restrict__ beta,
                            const float* __restrict__ w,
                            const float* __restrict__ A_log,
                            const float* __restrict__ dt_bias) {
    int gw   = (blockIdx.x * blockDim.x + threadIdx.x) >> 5;
    int lane = threadIdx.x & 31;
    if (gw >= TT * HH) return;
    int t = gw >> 4;
    int h = gw & 15;
    int d = lane * 4;
    int cq = h * DKK + d;

    float qy[4], ky[4], vy[4];
    conv_silu4(qkv, w, t, cq,        qy);
    conv_silu4(qkv, w, t, cq + 2048, ky);
    conv_silu4(qkv, w, t, cq + 4096, vy);

    // l2norm sums
    float sq = 0.f, sk = 0.f;
#pragma unroll
    for (int j = 0; j < 4; j++) {
        sq = fmaf(qy[j], qy[j], sq);
        sk = fmaf(ky[j], ky[j], sk);
    }
#pragma unroll
    for (int m = 16; m > 0; m >>= 1) {
        sq += __shfl_xor_sync(0xffffffffu, sq, m);
        sk += __shfl_xor_sync(0xffffffffu, sk, m);
    }
    float se_q = sq + 1e-6f, se_k = sk + 1e-6f;
    float rq = rsqrtf(se_q); rq = rq * (1.5f - 0.5f * se_q * rq * rq);  // Newton
    float rk = rsqrtf(se_k); rk = rk * (1.5f - 0.5f * se_k * rk * rk);
    rq *= 0.08838834764831845f;   // DK^-0.5

    // gate
    float ea = expf(A_log[h]);
    float4 fgv = *(const float4*)(fg + (size_t)t * (HH * DKK) + h * DKK + d);
    float4 dbv = *(const float4*)(dt_bias + h * DKK + d);
    float zf[4] = {fgv.x + dbv.x, fgv.y + dbv.y, fgv.z + dbv.z, fgv.w + dbv.w};

    float bb = 1.f / (1.f + expf(-beta[t * HH + h]));

    float qn[4], kn[4], av[4], kav[4];
#pragma unroll
    for (int j = 0; j < 4; j++) {
        float z  = zf[j];
        float sp = (z > 20.f) ? z : log1pf(expf(z));   // softplus
        av[j]  = expf(-ea * sp);                       // a = exp(g)
        qn[j]  = qy[j] * rq;
        kn[j]  = ky[j] * rk;
        kav[j] = kn[j] * av[j];
    }

    size_t pb = ((size_t)t * HH + h) * 512 + d;
    *(float4*)(g_P + pb      ) = make_float4(kav[0], kav[1], kav[2], kav[3]);
    *(float4*)(g_P + pb + 128) = make_float4(av[0],  av[1],  av[2],  av[3]);
    *(float4*)(g_P + pb + 256) = make_float4(kn[0],  kn[1],  kn[2],  kn[3]);
    *(float4*)(g_P + pb + 384) = make_float4(qn[0],  qn[1],  qn[2],  qn[3]);
    *(float4*)(g_BV + ((size_t)t * HH + h) * DKK + d) =
        make_float4(vy[0] * bb, vy[1] * bb, vy[2] * bb, vy[3] * bb);
    if (lane == 0)
        g_B[t * HH + h] = bb;
}

// --------------------------------------------------------------------------
// Kernel 1b: lookahead precompute. One warp per (t,h).
//   w_t = ka_t ∘ a_{t-1} ∘ a_{t-2}      (overwrite slot0 in place)
//   R_t = (ka_t ∘ a_{t-1}) · k_{t-2}    (scalar)
//   Q_t = ka_t · k_{t-1}                (scalar)
// Negative t indices: a := 1, k := 0.
// --------------------------------------------------------------------------
__global__ void pass2_kernel() {
    int gw   = (blockIdx.x * blockDim.x + threadIdx.x) >> 5;
    int lane = threadIdx.x & 31;
    if (gw >= TT * HH) return;
    int t = gw >> 4;
    int h = gw & 15;
    int d = lane * 4;

    size_t bt = ((size_t)t * HH + h) * 512;
    const size_t ts = (size_t)HH * 512;

    float4 ka = *(const float4*)(g_P + bt + d);
    float4 a1 = make_float4(1.f, 1.f, 1.f, 1.f);
    float4 a2 = make_float4(1.f, 1.f, 1.f, 1.f);
    float4 k1 = make_float4(0.f, 0.f, 0.f, 0.f);
    float4 k2 = make_float4(0.f, 0.f, 0.f, 0.f);
    if (t >= 1) {
        a1 = *(const float4*)(g_P + bt - ts + 128 + d);
        k1 = *(const float4*)(g_P + bt - ts + 256 + d);
    }
    if (t >= 2) {
        a2 = *(const float4*)(g_P + bt - 2 * ts + 128 + d);
        k2 = *(const float4*)(g_P + bt - 2 * ts + 256 + d);
    }
    float4 u = make_float4(ka.x * a1.x, ka.y * a1.y, ka.z * a1.z, ka.w * a1.w);
    float4 wv = make_float4(u.x * a2.x, u.y * a2.y, u.z * a2.z, u.w * a2.w);

    float rp = fmaf(u.x, k2.x, u.y * k2.y) + fmaf(u.z, k2.z, u.w * k2.w);
    float qp = fmaf(ka.x, k1.x, ka.y * k1.y) + fmaf(ka.z, k1.z, ka.w * k1.w);
#pragma unroll
    for (int m = 16; m > 0; m >>= 1) {
        rp += __shfl_xor_sync(0xffffffffu, rp, m);
        qp += __shfl_xor_sync(0xffffffffu, qp, m);
    }
    *(float4*)(g_P + bt + d) = wv;            // slot0 := w (safe: private)
    if (lane == 0)
        *(float4*)(g_S4 + ((size_t)t * HH + h) * 4) =
            make_float4(g_B[t * HH + h], rp, qp, 0.f);
}

// --------------------------------------------------------------------------
// Kernel 2: gated delta-rule recurrence with 3-step lookahead.
// Grid 128 CTAs (same g_P streaming as R8) x 512 threads: 16 warps/CTA,
// ONE v-column per warp -> 2048 warps total, 4 warps/SMSP for latency hiding.
// Lane owns k-quad 4*lane..4*lane+3 (distinct-per-lane LDS.128).
// State S0,S1 = S[4 ki][col] as f32x2 pairs.
//
// Critical chain per step: 3 dependent scalar FFMAs:
//   r_t = P_t + d2*R_t + d1*Q_t;  dt = bv_t - b_t*r_t
// P_{t+3} = w_{t+3}.S_t reduced off-chain (3-step slack); o-dot direct.
// Two scalar 5-level butterflies (o, p), interleaved.
// --------------------------------------------------------------------------
#define STGF 544   // floats per stage: 512 packed + 16 bv + 4 scalars + pad
#define NSTG 32    // 4 groups x 8 steps in-flight ring
#define SMEM_BYTES (NSTG * STGF * 4)   // 69632 B (dynamic)

__global__ void __launch_bounds__(512)
recur_kernel(float* __restrict__ out) {
    extern __shared__ __align__(16) float sm[];

    const int tid  = threadIdx.x;
    const int warp = tid >> 5;                    // 0..15 = column in slab
    const int lane = tid & 31;
    const int h    = blockIdx.x >> 3;
    const int vb   = (blockIdx.x & 7) * 16;       // CTA's 16-column slab
    float* outp = out + h * DKK + vb + warp;      // scalar per (t, warp)

    auto issue = [&](int g) {
#pragma unroll
        for (int s = 0; s < 8; s++) {
            int tu = 8 * g + s;
            float* sp = sm + (tu & 31) * STGF;
            int t = (tu > TT - 1) ? (TT - 1) : tu;
            const float* gp = g_P + ((size_t)t * HH + h) * 512;
            if (tid < 128) cp16(sp + tid * 4, gp + tid * 4);
            else if (tid < 132)
                cp16(sp + 512 + (tid - 128) * 4,
                     g_BV + ((size_t)t * HH + h) * DKK + vb + (tid - 128) * 4);
            else if (tid == 132)
                cp16(sp + 528, g_S4 + ((size_t)t * HH + h) * 4);
        }
        asm volatile("cp.async.commit_group;" ::: "memory");
    };

    issue(0); issue(1); issue(2);

    ull S0 = 0, S1 = 0;                     // S[8 ki][col] as 4 f32x2 pairs
    float Pq[4] = {0.f, 0.f, 0.f, 0.f};     // reduced P for steps t..t+3
    float d1 = 0.f, d2 = 0.f;               // delta_{t-1}, delta_{t-2}

    for (int g = 0; g < TT / 8; g++) {
        // all but newest group complete -> groups g and g+1 ready
        asm volatile("cp.async.wait_group 1;" ::: "memory");
        __syncthreads();
#pragma unroll
        for (int s = 0; s < 8; s++) {
            const int t = 8 * g + s;
            const float* spb = sm + (t & 31) * STGF;
            const float* spn = sm + ((t + 3) & 31) * STGF;  // w_{t+3}
            const int lo = lane * 4;

            // distinct-per-lane array loads (one LDS.128 per array)
            ulonglong2 A = *(const ulonglong2*)(spb + 128 + lo);
            ulonglong2 K = *(const ulonglong2*)(spb + 256 + lo);
            ulonglong2 Q = *(const ulonglong2*)(spb + 384 + lo);
            ulonglong2 W = *(const ulonglong2*)(spn + lo);

            float4 s4 = *(const float4*)(spb + 528);    // {b, R, Q, -}
            float  bv = spb[512 + warp];

            // ---- critical chain: 3 dependent scalar FFMAs ----
            float r  = fmaf(d2, s4.y, Pq[t & 3]);
            r        = fmaf(d1, s4.z, r);
            float dt = fmaf(-s4.x, r, bv);
            d2 = d1; d1 = dt;
            ull D = pack2(dt);

            // ---- off-chain: S update + o-dot + P_{t+3}-dot ----
            S0 = ffma2(A.x, S0, fmul2(K.x, D));
            S1 = ffma2(A.y, S1, fmul2(K.y, D));
            float op = hsum2(ffma2(Q.x, S0, fmul2(Q.y, S1)));
            float pp = hsum2(ffma2(W.x, S0, fmul2(W.y, S1)));

            // two interleaved scalar 5-level butterflies (off-chain)
#pragma unroll
            for (int m = 1; m < 32; m <<= 1) {
                op += __shfl_xor_sync(0xffffffffu, op, m);
                pp += __shfl_xor_sync(0xffffffffu, pp, m);
            }
            Pq[(t + 3) & 3] = pp;           // P_{t+3} = w_{t+3} . S_t
            if (lane == 0)
                outp[(size_t)t * (HH * DKK)] = op;
        }
        issue(g + 3);
    }
}

// --------------------------------------------------------------------------
extern "C" void kernel_launch(void* const* d_in, const int* in_sizes, int n_in,
                              void* d_out, int out_size) {
    const float* mixed_qkv   = (const float*)d_in[0];
    const float* forget_gate = (const float*)d_in[1];
    const float* beta        = (const float*)d_in[2];
    const float* conv_w      = (const float*)d_in[3];
    const float* A_log       = (const float*)d_in[4];
    const float* dt_bias     = (const float*)d_in[5];
    float* out = (float*)d_out;

    cudaFuncSetAttribute(recur_kernel,
                         cudaFuncAttributeMaxDynamicSharedMemorySize,
                         SMEM_BYTES);

    // 65536 (t,h) warps, 8 per 256-thread block
    prep_kernel<<<(TT * HH) / 8, 256>>>(mixed_qkv, forget_gate, beta,
                                        conv_w, A_log, dt_bias);
    pass2_kernel<<<(TT * HH) / 8, 256>>>();
    recur_kernel<<<128, 512, SMEM_BYTES>>>(out);
}

// round 14
// speedup vs baseline: 1.8820x; 1.8820x over previous
#include <cuda_runtime.h>
#include <cuda_bf16.h>

// Problem constants
#define TT   4096
#define HH   16
#define DKK  128
#define QKVC 6144
#define NELEM (TT * HH * DKK)   // 8388608

// Scratch (static __device__ globals — no runtime allocation)
// g_P packed per (t,h): [slot0(128) | a(128) | k(128) | q(128)]
// slot0 holds ka after prep; pass2 overwrites it in place with
// w_t = ka_t ∘ a_{t-1} ∘ a_{t-2} (only warp (t,h) ever touches slot0 of (t,h)).
__device__ __align__(16) float g_P [TT * HH * 512];
__device__ __align__(16) float g_BV[NELEM];        // b * (conv+silu v)
__device__ __align__(16) float g_S4[TT * HH * 4];  // {b, R, Q, 0} per (t,h)
__device__ float g_B[TT * HH];                     // sigmoid(beta)

typedef unsigned long long ull;

// --------------------------------------------------------------------------
// f32x2 packed-math helpers (FFMA2 path; ptxas only emits via PTX f32x2)
// --------------------------------------------------------------------------
__device__ __forceinline__ ull ffma2(ull a, ull b, ull c) {
    ull d;
    asm("fma.rn.f32x2 %0, %1, %2, %3;" : "=l"(d) : "l"(a), "l"(b), "l"(c));
    return d;
}
__device__ __forceinline__ ull fmul2(ull a, ull b) {
    ull d;
    asm("mul.rn.f32x2 %0, %1, %2;" : "=l"(d) : "l"(a), "l"(b));
    return d;
}
__device__ __forceinline__ float hsum2(ull a) {
    float lo, hi;
    asm("mov.b64 {%0, %1}, %2;" : "=f"(lo), "=f"(hi) : "l"(a));
    return lo + hi;
}
__device__ __forceinline__ ull pack2(float x) {
    ull d;
    asm("mov.b64 %0, {%1, %1};" : "=l"(d) : "f"(x));
    return d;
}
__device__ __forceinline__ ull packAB(float a, float b) {
    ull d;
    asm("mov.b64 %0, {%1, %2};" : "=l"(d) : "f"(a), "f"(b));
    return d;
}
__device__ __forceinline__ void unpack2(float& lo, float& hi, ull a) {
    asm("mov.b64 {%0, %1}, %2;" : "=f"(lo), "=f"(hi) : "l"(a));
}

// cp.async helper
__device__ __forceinline__ void cp16(float* dst, const float* src) {
    unsigned d = (unsigned)__cvta_generic_to_shared(dst);
    asm volatile("cp.async.cg.shared.global [%0], [%1], 16;"
                 :: "r"(d), "l"(src) : "memory");
}

// --------------------------------------------------------------------------
// Kernel 1: conv1d(K=4, depthwise, causal) + SiLU + l2norm + gate precompute
// One warp per (t, h); lane handles 4 consecutive d via float4.
// --------------------------------------------------------------------------
__device__ __forceinline__ void conv_silu4(const float* __restrict__ x,
                                           const float* __restrict__ w,
                                           int t, int c, float out[4]) {
    float wz[4][4];
#pragma unroll
    for (int j = 0; j < 4; j++) {
        float4 wv = *(const float4*)(w + (size_t)(c + j) * 4);
        wz[j][0] = wv.x; wz[j][1] = wv.y; wz[j][2] = wv.z; wz[j][3] = wv.w;
    }
    float acc[4] = {0.f, 0.f, 0.f, 0.f};
#pragma unroll
    for (int tau = 0; tau < 4; tau++) {
        int tt = t - 3 + tau;
        if (tt >= 0) {
            float4 xv = *(const float4*)(x + (size_t)tt * QKVC + c);
            acc[0] = fmaf(xv.x, wz[0][tau], acc[0]);
            acc[1] = fmaf(xv.y, wz[1][tau], acc[1]);
            acc[2] = fmaf(xv.z, wz[2][tau], acc[2]);
            acc[3] = fmaf(xv.w, wz[3][tau], acc[3]);
        }
    }
#pragma unroll
    for (int j = 0; j < 4; j++)
        out[j] = acc[j] / (1.f + expf(-acc[j]));   // SiLU
}

__global__ void prep_kernel(const float* __restrict__ qkv,
                            const float* __restrict__ fg,
                            const float* __restrict__ beta,
                            const float* __restrict__ w,
                            const float* __restrict__ A_log,
                            const float* __restrict__ dt_bias) {
    int gw   = (blockIdx.x * blockDim.x + threadIdx.x) >> 5;
    int lane = threadIdx.x & 31;
    if (gw >= TT * HH) return;
    int t = gw >> 4;
    int h = gw & 15;
    int d = lane * 4;
    int cq = h * DKK + d;

    float qy[4], ky[4], vy[4];
    conv_silu4(qkv, w, t, cq,        qy);
    conv_silu4(qkv, w, t, cq + 2048, ky);
    conv_silu4(qkv, w, t, cq + 4096, vy);

    // l2norm sums
    float sq = 0.f, sk = 0.f;
#pragma unroll
    for (int j = 0; j < 4; j++) {
        sq = fmaf(qy[j], qy[j], sq);
        sk = fmaf(ky[j], ky[j], sk);
    }
#pragma unroll
    for (int m = 16; m > 0; m >>= 1) {
        sq += __shfl_xor_sync(0xffffffffu, sq, m);
        sk += __shfl_xor_sync(0xffffffffu, sk, m);
    }
    float se_q = sq + 1e-6f, se_k = sk + 1e-6f;
    float rq = rsqrtf(se_q); rq = rq * (1.5f - 0.5f * se_q * rq * rq);  // Newton
    float rk = rsqrtf(se_k); rk = rk * (1.5f - 0.5f * se_k * rk * rk);
    rq *= 0.08838834764831845f;   // DK^-0.5

    // gate
    float ea = expf(A_log[h]);
    float4 fgv = *(const float4*)(fg + (size_t)t * (HH * DKK) + h * DKK + d);
    float4 dbv = *(const float4*)(dt_bias + h * DKK + d);
    float zf[4] = {fgv.x + dbv.x, fgv.y + dbv.y, fgv.z + dbv.z, fgv.w + dbv.w};

    float bb = 1.f / (1.f + expf(-beta[t * HH + h]));

    float qn[4], kn[4], av[4], kav[4];
#pragma unroll
    for (int j = 0; j < 4; j++) {
        float z  = zf[j];
        float sp = (z > 20.f) ? z : log1pf(expf(z));   // softplus
        av[j]  = expf(-ea * sp);                       // a = exp(g)
        qn[j]  = qy[j] * rq;
        kn[j]  = ky[j] * rk;
        kav[j] = kn[j] * av[j];
    }

    size_t pb = ((size_t)t * HH + h) * 512 + d;
    *(float4*)(g_P + pb      ) = make_float4(kav[0], kav[1], kav[2], kav[3]);
    *(float4*)(g_P + pb + 128) = make_float4(av[0],  av[1],  av[2],  av[3]);
    *(float4*)(g_P + pb + 256) = make_float4(kn[0],  kn[1],  kn[2],  kn[3]);
    *(float4*)(g_P + pb + 384) = make_float4(qn[0],  qn[1],  qn[2],  qn[3]);
    *(float4*)(g_BV + ((size_t)t * HH + h) * DKK + d) =
        make_float4(vy[0] * bb, vy[1] * bb, vy[2] * bb, vy[3] * bb);
    if (lane == 0)
        g_B[t * HH + h] = bb;
}

// --------------------------------------------------------------------------
// Kernel 1b: lookahead precompute. One warp per (t,h).
//   w_t = ka_t ∘ a_{t-1} ∘ a_{t-2}      (overwrite slot0 in place)
//   R_t = (ka_t ∘ a_{t-1}) · k_{t-2}    (scalar)
//   Q_t = ka_t · k_{t-1}                (scalar)
// Negative t indices: a := 1, k := 0.
// --------------------------------------------------------------------------
__global__ void pass2_kernel() {
    int gw   = (blockIdx.x * blockDim.x + threadIdx.x) >> 5;
    int lane = threadIdx.x & 31;
    if (gw >= TT * HH) return;
    int t = gw >> 4;
    int h = gw & 15;
    int d = lane * 4;

    size_t bt = ((size_t)t * HH + h) * 512;
    const size_t ts = (size_t)HH * 512;

    float4 ka = *(const float4*)(g_P + bt + d);
    float4 a1 = make_float4(1.f, 1.f, 1.f, 1.f);
    float4 a2 = make_float4(1.f, 1.f, 1.f, 1.f);
    float4 k1 = make_float4(0.f, 0.f, 0.f, 0.f);
    float4 k2 = make_float4(0.f, 0.f, 0.f, 0.f);
    if (t >= 1) {
        a1 = *(const float4*)(g_P + bt - ts + 128 + d);
        k1 = *(const float4*)(g_P + bt - ts + 256 + d);
    }
    if (t >= 2) {
        a2 = *(const float4*)(g_P + bt - 2 * ts + 128 + d);
        k2 = *(const float4*)(g_P + bt - 2 * ts + 256 + d);
    }
    float4 u = make_float4(ka.x * a1.x, ka.y * a1.y, ka.z * a1.z, ka.w * a1.w);
    float4 wv = make_float4(u.x * a2.x, u.y * a2.y, u.z * a2.z, u.w * a2.w);

    float rp = fmaf(u.x, k2.x, u.y * k2.y) + fmaf(u.z, k2.z, u.w * k2.w);
    float qp = fmaf(ka.x, k1.x, ka.y * k1.y) + fmaf(ka.z, k1.z, ka.w * k1.w);
#pragma unroll
    for (int m = 16; m > 0; m >>= 1) {
        rp += __shfl_xor_sync(0xffffffffu, rp, m);
        qp += __shfl_xor_sync(0xffffffffu, qp, m);
    }
    *(float4*)(g_P + bt + d) = wv;            // slot0 := w (safe: private)
    if (lane == 0)
        *(float4*)(g_S4 + ((size_t)t * HH + h) * 4) =
            make_float4(g_B[t * HH + h], rp, qp, 0.f);
}

// --------------------------------------------------------------------------
// Kernel 2: gated delta-rule recurrence with 3-step lookahead (R8 grid/math).
// CTA = 256 threads (8 warps) = 16 v-columns; one warp = 2 v-columns.
// Lane owns k-quad 4*lane..4*lane+3 (distinct-per-lane LDS.128).
// Change vs R8: the 4-value reduction (oA,oB,pA,pB) uses a split-butterfly:
//   levels 16,8 exchange DIFFERENT values via SEL (one SHFL each pair),
//   levels 4,2,1 plain -> 6 SHFL total; + 3 idx-broadcasts = 9 SHFL vs 20.
// Result placement: oA in lanes 0-7, oB in 8-15, pA in 16-23, pB in 24-31.
// Critical chain per step: 3 dependent packed FFMA2s:
//   r_t = P_t + d2*R_t + d1*Q_t;  dt = bv_t - b_t*r_t
// P_{t+3} = w_{t+3}.S_t reduced off-chain (3-step slack).
// --------------------------------------------------------------------------
#define STGF 544   // floats per stage: 512 packed + 16 bv + 4 scalars + pad
#define NST  16    // 4 groups x 4 steps in-flight ring

__global__ void __launch_bounds__(256, 1)
recur_kernel(float* __restrict__ out) {
    __shared__ __align__(16) float sm[NST * STGF];

    const int tid  = threadIdx.x;
    const int warp = tid >> 5;
    const int lane = tid & 31;
    const int h    = blockIdx.x >> 3;
    const int vb   = (blockIdx.x & 7) * 16;       // CTA's 16-column slab
    float* outp = out + h * DKK + vb + warp * 2;  // float2 per (t, warp)

    auto issue = [&](int g) {
#pragma unroll
        for (int s = 0; s < 4; s++) {
            int tu = 4 * g + s;
            float* sp = sm + (tu & 15) * STGF;
            int t = (tu > TT - 1) ? (TT - 1) : tu;
            const float* gp = g_P + ((size_t)t * HH + h) * 512;
            if (tid < 128) cp16(sp + tid * 4, gp + tid * 4);
            if (tid >= 128 && tid < 132)
                cp16(sp + 512 + (tid - 128) * 4,
                     g_BV + ((size_t)t * HH + h) * DKK + vb + (tid - 128) * 4);
            if (tid == 132)
                cp16(sp + 528, g_S4 + ((size_t)t * HH + h) * 4);
        }
        asm volatile("cp.async.commit_group;" ::: "memory");
    };

    issue(0); issue(1); issue(2);

    ull SA0 = 0, SA1 = 0, SB0 = 0, SB1 = 0;
    ull Pq[4] = {0, 0, 0, 0};     // packed reduced P for steps t..t+3
    ull d1 = 0, d2 = 0;           // packed delta_{t-1}, delta_{t-2}
    const bool lo16 = (lane < 16);
    const bool lo8  = ((lane & 8) == 0);

    for (int g = 0; g < TT / 4; g++) {
        // groups g and g+1 complete (w of t+3 lives in group g+1)
        asm volatile("cp.async.wait_group 1;" ::: "memory");
        __syncthreads();
#pragma unroll
        for (int s = 0; s < 4; s++) {
            const int t = 4 * g + s;
            const float* spb = sm + (t & 15) * STGF;
            const float* spn = sm + ((t + 3) & 15) * STGF;  // w_{t+3}
            const int lo = lane * 4;

            // distinct-per-lane array loads (one LDS.128 per array)
            ulonglong2 A = *(const ulonglong2*)(spb + 128 + lo);
            ulonglong2 K = *(const ulonglong2*)(spb + 256 + lo);
            ulonglong2 Q = *(const ulonglong2*)(spb + 384 + lo);
            ulonglong2 W = *(const ulonglong2*)(spn + lo);

            float4 s4 = *(const float4*)(spb + 528);    // {b, R, Q, -}
            ull R2  = pack2(s4.y);
            ull Q2  = pack2(s4.z);
            ull nB2 = pack2(-s4.x);
            ull BV2 = *(const ull*)(spb + 512 + warp * 2);  // (colA,colB)

            // ---- critical chain: 3 dependent packed FFMA2s ----
            ull r  = ffma2(d2, R2, Pq[t & 3]);
            r      = ffma2(d1, Q2, r);
            ull dt = ffma2(nB2, r, BV2);
            d2 = d1; d1 = dt;
            float dA, dB; unpack2(dA, dB, dt);
            ull DA = pack2(dA), DB = pack2(dB);

            // ---- off-chain: S update + o-dot + P_{t+3}-dot ----
            SA0 = ffma2(A.x, SA0, fmul2(K.x, DA));
            SA1 = ffma2(A.y, SA1, fmul2(K.y, DA));
            SB0 = ffma2(A.x, SB0, fmul2(K.x, DB));
            SB1 = ffma2(A.y, SB1, fmul2(K.y, DB));

            float oA = hsum2(ffma2(Q.x, SA0, fmul2(Q.y, SA1)));
            float oB = hsum2(ffma2(Q.x, SB0, fmul2(Q.y, SB1)));
            float pA = hsum2(ffma2(W.x, SA0, fmul2(W.y, SA1)));
            float pB = hsum2(ffma2(W.x, SB0, fmul2(W.y, SB1)));

            // ---- 4-value split-butterfly: 6 SHFL ----
            // level 16: pairs (oA,pA) and (oB,pB)
            float t1 = lo16 ? pA : oA;
            float r1 = __shfl_xor_sync(0xffffffffu, t1, 16);
            float u  = (lo16 ? oA : pA) + r1;
            float t2 = lo16 ? pB : oB;
            float r2 = __shfl_xor_sync(0xffffffffu, t2, 16);
            float w2 = (lo16 ? oB : pB) + r2;
            // level 8: split (u, w2)
            float t3 = lo8 ? w2 : u;
            float r3 = __shfl_xor_sync(0xffffffffu, t3, 8);
            float v  = (lo8 ? u : w2) + r3;
            // levels 4,2,1: plain butterfly within 8-lane group
            v += __shfl_xor_sync(0xffffffffu, v, 4);
            v += __shfl_xor_sync(0xffffffffu, v, 2);
            v += __shfl_xor_sync(0xffffffffu, v, 1);
            // v: lanes 0-7 = oA, 8-15 = oB, 16-23 = pA, 24-31 = pB

            float pAr = __shfl_sync(0xffffffffu, v, 16);
            float pBr = __shfl_sync(0xffffffffu, v, 24);
            Pq[(t + 3) & 3] = packAB(pAr, pBr); // P_{t+3} = w_{t+3} . S_t
            float oBr = __shfl_sync(0xffffffffu, v, 8);
            if (lane == 0)
                *(float2*)(outp + (size_t)t * (HH * DKK)) = make_float2(v, oBr);
        }
        issue(g + 3);
    }
}

// --------------------------------------------------------------------------
extern "C" void kernel_launch(void* const* d_in, const int* in_sizes, int n_in,
                              void* d_out, int out_size) {
    const float* mixed_qkv   = (const float*)d_in[0];
    const float* forget_gate = (const float*)d_in[1];
    const float* beta        = (const float*)d_in[2];
    const float* conv_w      = (const float*)d_in[3];
    const float* A_log       = (const float*)d_in[4];
    const float* dt_bias     = (const float*)d_in[5];
    float* out = (float*)d_out;

    prep_kernel<<<(TT * HH) / 8, 256>>>(mixed_qkv, forget_gate, beta,
                                        conv_w, A_log, dt_bias);
    pass2_kernel<<<(TT * HH) / 8, 256>>>();
    recur_kernel<<<128, 256>>>(out);
}

// round 15
// speedup vs baseline: 1.8826x; 1.0003x over previous
#include <cuda_runtime.h>
#include <cuda_bf16.h>

// Problem constants
#define TT   4096
#define HH   16
#define DKK  128
#define QKVC 6144
#define NELEM (TT * HH * DKK)   // 8388608

// Scratch (static __device__ globals — no runtime allocation)
// g_P packed per (t,h): [slot0(128) | a(128) | k(128) | q(128)]
// slot0 holds ka after prep; pass2 overwrites it in place with
// w_t = ka_t ∘ a_{t-1} ∘ a_{t-2} (only warp (t,h) ever touches slot0 of (t,h)).
__device__ __align__(16) float g_P [TT * HH * 512];
__device__ __align__(16) float g_BV[NELEM];        // b * (conv+silu v)
__device__ __align__(16) float g_S4[TT * HH * 4];  // {b, R, Q, 0} per (t,h)
__device__ float g_B[TT * HH];                     // sigmoid(beta)

typedef unsigned long long ull;

// --------------------------------------------------------------------------
// f32x2 packed-math helpers (FFMA2 path; ptxas only emits via PTX f32x2)
// --------------------------------------------------------------------------
__device__ __forceinline__ ull ffma2(ull a, ull b, ull c) {
    ull d;
    asm("fma.rn.f32x2 %0, %1, %2, %3;" : "=l"(d) : "l"(a), "l"(b), "l"(c));
    return d;
}
__device__ __forceinline__ ull fmul2(ull a, ull b) {
    ull d;
    asm("mul.rn.f32x2 %0, %1, %2;" : "=l"(d) : "l"(a), "l"(b));
    return d;
}
__device__ __forceinline__ float hsum2(ull a) {
    float lo, hi;
    asm("mov.b64 {%0, %1}, %2;" : "=f"(lo), "=f"(hi) : "l"(a));
    return lo + hi;
}
__device__ __forceinline__ ull pack2(float x) {
    ull d;
    asm("mov.b64 %0, {%1, %1};" : "=l"(d) : "f"(x));
    return d;
}

// cp.async helper
__device__ __forceinline__ void cp16(float* dst, const float* src) {
    unsigned d = (unsigned)__cvta_generic_to_shared(dst);
    asm volatile("cp.async.cg.shared.global [%0], [%1], 16;"
                 :: "r"(d), "l"(src) : "memory");
}

// --------------------------------------------------------------------------
// Kernel 1: conv1d(K=4, depthwise, causal) + SiLU + l2norm + gate precompute
// One warp per (t, h); lane handles 4 consecutive d via float4.
// --------------------------------------------------------------------------
__device__ __forceinline__ void conv_silu4(const float* __restrict__ x,
                                           const float* __restrict__ w,
                                           int t, int c, float out[4]) {
    float wz[4][4];
#pragma unroll
    for (int j = 0; j < 4; j++) {
        float4 wv = *(const float4*)(w + (size_t)(c + j) * 4);
        wz[j][0] = wv.x; wz[j][1] = wv.y; wz[j][2] = wv.z; wz[j][3] = wv.w;
    }
    float acc[4] = {0.f, 0.f, 0.f, 0.f};
#pragma unroll
    for (int tau = 0; tau < 4; tau++) {
        int tt = t - 3 + tau;
        if (tt >= 0) {
            float4 xv = *(const float4*)(x + (size_t)tt * QKVC + c);
            acc[0] = fmaf(xv.x, wz[0][tau], acc[0]);
            acc[1] = fmaf(xv.y, wz[1][tau], acc[1]);
            acc[2] = fmaf(xv.z, wz[2][tau], acc[2]);
            acc[3] = fmaf(xv.w, wz[3][tau], acc[3]);
        }
    }
#pragma unroll
    for (int j = 0; j < 4; j++)
        out[j] = acc[j] / (1.f + expf(-acc[j]));   // SiLU
}

__global__ void prep_kernel(const float* __restrict__ qkv,
                            const float* __restrict__ fg,
                            const float* __restrict__ beta,
                            const float* __restrict__ w,
                            const float* __restrict__ A_log,
                            const float* __restrict__ dt_bias) {
    int gw   = (blockIdx.x * blockDim.x + threadIdx.x) >> 5;
    int lane = threadIdx.x & 31;
    if (gw >= TT * HH) return;
    int t = gw >> 4;
    int h = gw & 15;
    int d = lane * 4;
    int cq = h * DKK + d;

    float qy[4], ky[4], vy[4];
    conv_silu4(qkv, w, t, cq,        qy);
    conv_silu4(qkv, w, t, cq + 2048, ky);
    conv_silu4(qkv, w, t, cq + 4096, vy);

    // l2norm sums
    float sq = 0.f, sk = 0.f;
#pragma unroll
    for (int j = 0; j < 4; j++) {
        sq = fmaf(qy[j], qy[j], sq);
        sk = fmaf(ky[j], ky[j], sk);
    }
#pragma unroll
    for (int m = 16; m > 0; m >>= 1) {
        sq += __shfl_xor_sync(0xffffffffu, sq, m);
        sk += __shfl_xor_sync(0xffffffffu, sk, m);
    }
    float se_q = sq + 1e-6f, se_k = sk + 1e-6f;
    float rq = rsqrtf(se_q); rq = rq * (1.5f - 0.5f * se_q * rq * rq);  // Newton
    float rk = rsqrtf(se_k); rk = rk * (1.5f - 0.5f * se_k * rk * rk);
    rq *= 0.08838834764831845f;   // DK^-0.5

    // gate
    float ea = expf(A_log[h]);
    float4 fgv = *(const float4*)(fg + (size_t)t * (HH * DKK) + h * DKK + d);
    float4 dbv = *(const float4*)(dt_bias + h * DKK + d);
    float zf[4] = {fgv.x + dbv.x, fgv.y + dbv.y, fgv.z + dbv.z, fgv.w + dbv.w};

    float bb = 1.f / (1.f + expf(-beta[t * HH + h]));

    float qn[4], kn[4], av[4], kav[4];
#pragma unroll
    for (int j = 0; j < 4; j++) {
        float z  = zf[j];
        float sp = (z > 20.f) ? z : log1pf(expf(z));   // softplus
        av[j]  = expf(-ea * sp);                       // a = exp(g)
        qn[j]  = qy[j] * rq;
        kn[j]  = ky[j] * rk;
        kav[j] = kn[j] * av[j];
    }

    size_t pb = ((size_t)t * HH + h) * 512 + d;
    *(float4*)(g_P + pb      ) = make_float4(kav[0], kav[1], kav[2], kav[3]);
    *(float4*)(g_P + pb + 128) = make_float4(av[0],  av[1],  av[2],  av[3]);
    *(float4*)(g_P + pb + 256) = make_float4(kn[0],  kn[1],  kn[2],  kn[3]);
    *(float4*)(g_P + pb + 384) = make_float4(qn[0],  qn[1],  qn[2],  qn[3]);
    *(float4*)(g_BV + ((size_t)t * HH + h) * DKK + d) =
        make_float4(vy[0] * bb, vy[1] * bb, vy[2] * bb, vy[3] * bb);
    if (lane == 0)
        g_B[t * HH + h] = bb;
}

// --------------------------------------------------------------------------
// Kernel 1b: lookahead precompute. One warp per (t,h).
//   w_t = ka_t ∘ a_{t-1} ∘ a_{t-2}      (overwrite slot0 in place)
//   R_t = (ka_t ∘ a_{t-1}) · k_{t-2}    (scalar)
//   Q_t = ka_t · k_{t-1}                (scalar)
// Negative t indices: a := 1, k := 0.
// --------------------------------------------------------------------------
__global__ void pass2_kernel() {
    int gw   = (blockIdx.x * blockDim.x + threadIdx.x) >> 5;
    int lane = threadIdx.x & 31;
    if (gw >= TT * HH) return;
    int t = gw >> 4;
    int h = gw & 15;
    int d = lane * 4;

    size_t bt = ((size_t)t * HH + h) * 512;
    const size_t ts = (size_t)HH * 512;

    float4 ka = *(const float4*)(g_P + bt + d);
    float4 a1 = make_float4(1.f, 1.f, 1.f, 1.f);
    float4 a2 = make_float4(1.f, 1.f, 1.f, 1.f);
    float4 k1 = make_float4(0.f, 0.f, 0.f, 0.f);
    float4 k2 = make_float4(0.f, 0.f, 0.f, 0.f);
    if (t >= 1) {
        a1 = *(const float4*)(g_P + bt - ts + 128 + d);
        k1 = *(const float4*)(g_P + bt - ts + 256 + d);
    }
    if (t >= 2) {
        a2 = *(const float4*)(g_P + bt - 2 * ts + 128 + d);
        k2 = *(const float4*)(g_P + bt - 2 * ts + 256 + d);
    }
    float4 u = make_float4(ka.x * a1.x, ka.y * a1.y, ka.z * a1.z, ka.w * a1.w);
    float4 wv = make_float4(u.x * a2.x, u.y * a2.y, u.z * a2.z, u.w * a2.w);

    float rp = fmaf(u.x, k2.x, u.y * k2.y) + fmaf(u.z, k2.z, u.w * k2.w);
    float qp = fmaf(ka.x, k1.x, ka.y * k1.y) + fmaf(ka.z, k1.z, ka.w * k1.w);
#pragma unroll
    for (int m = 16; m > 0; m >>= 1) {
        rp += __shfl_xor_sync(0xffffffffu, rp, m);
        qp += __shfl_xor_sync(0xffffffffu, qp, m);
    }
    *(float4*)(g_P + bt + d) = wv;            // slot0 := w (safe: private)
    if (lane == 0)
        *(float4*)(g_S4 + ((size_t)t * HH + h) * 4) =
            make_float4(g_B[t * HH + h], rp, qp, 0.f);
}

// --------------------------------------------------------------------------
// Kernel 2: gated delta-rule recurrence with 3-step lookahead.
// CTA = 256 threads (8 warps) = 16 v-columns; one warp = 2 v-columns.
// Lane owns k-quad 4*lane..4*lane+3 (distinct-per-lane LDS.128).
//
// R15 change vs R14: scalar HALF-LANE chain.
//   Lanes 0-15 run column A's recurrence chain; lanes 16-31 column B's.
//   - P routing: ONE shfl.idx with precomputed per-lane index (was 2
//     broadcasts + pack).
//   - chain: 3 scalar FFMAs on s4 scalars directly (kills 3 pack2).
//   - dt exchange for S-update: ONE shfl.xor(dt,16) + 2 SEL.
//   - o store: predicated scalar STG from lanes 0 and 8 (kills oB bcast).
// 4-value split-butterfly reduction (6 SHFL) unchanged from R14.
// --------------------------------------------------------------------------
#define STGF 544   // floats per stage: 512 packed + 16 bv + 4 scalars + pad
#define NST  16    // 4 groups x 4 steps in-flight ring

__global__ void __launch_bounds__(256, 1)
recur_kernel(float* __restrict__ out) {
    __shared__ __align__(16) float sm[NST * STGF];

    const int tid  = threadIdx.x;
    const int warp = tid >> 5;
    const int lane = tid & 31;
    const int h    = blockIdx.x >> 3;
    const int vb   = (blockIdx.x & 7) * 16;       // CTA's 16-column slab
    float* outp = out + h * DKK + vb + warp * 2;

    auto issue = [&](int g) {
#pragma unroll
        for (int s = 0; s < 4; s++) {
            int tu = 4 * g + s;
            float* sp = sm + (tu & 15) * STGF;
            int t = (tu > TT - 1) ? (TT - 1) : tu;
            const float* gp = g_P + ((size_t)t * HH + h) * 512;
            if (tid < 128) cp16(sp + tid * 4, gp + tid * 4);
            if (tid >= 128 && tid < 132)
                cp16(sp + 512 + (tid - 128) * 4,
                     g_BV + ((size_t)t * HH + h) * DKK + vb + (tid - 128) * 4);
            if (tid == 132)
                cp16(sp + 528, g_S4 + ((size_t)t * HH + h) * 4);
        }
        asm volatile("cp.async.commit_group;" ::: "memory");
    };

    issue(0); issue(1); issue(2);

    ull SA0 = 0, SA1 = 0, SB0 = 0, SB1 = 0;
    float Pq[4] = {0.f, 0.f, 0.f, 0.f};   // per-half reduced P, steps t..t+3
    float d1 = 0.f, d2 = 0.f;             // per-half delta_{t-1}, delta_{t-2}
    const bool lo16 = (lane < 16);
    const bool lo8  = ((lane & 8) == 0);
    // shfl.idx source: lanes 0-15 fetch pA (lanes 16-23), 16-31 fetch pB (24-31)
    const int  psrc = 16 | ((lane & 16) >> 1) | (lane & 7);
    // per-half bv smem offset: col A for lanes 0-15, col B for lanes 16-31
    const int  bvix = 512 + warp * 2 + (lane >> 4);
    // predicated scalar store: lane 0 -> col A, lane 8 -> col B
    float* sout = outp + ((lane >> 3) & 1);
    const bool do_store = (lane == 0) || (lane == 8);

    for (int g = 0; g < TT / 4; g++) {
        // groups g and g+1 complete (w of t+3 lives in group g+1)
        asm volatile("cp.async.wait_group 1;" ::: "memory");
        __syncthreads();
#pragma unroll
        for (int s = 0; s < 4; s++) {
            const int t = 4 * g + s;
            const float* spb = sm + (t & 15) * STGF;
            const float* spn = sm + ((t + 3) & 15) * STGF;  // w_{t+3}
            const int lo = lane * 4;

            // distinct-per-lane array loads (one LDS.128 per array)
            ulonglong2 A = *(const ulonglong2*)(spb + 128 + lo);
            ulonglong2 K = *(const ulonglong2*)(spb + 256 + lo);
            ulonglong2 Q = *(const ulonglong2*)(spb + 384 + lo);
            ulonglong2 W = *(const ulonglong2*)(spn + lo);

            float4 s4 = *(const float4*)(spb + 528);    // {b, R, Q, -}
            float  bv = spb[bvix];                      // per-half column bv

            // ---- critical chain: 3 dependent scalar FFMAs (per half) ----
            float r  = fmaf(d2, s4.y, Pq[t & 3]);
            r        = fmaf(d1, s4.z, r);
            float dt = fmaf(-s4.x, r, bv);
            d2 = d1; d1 = dt;

            // exchange dt across halves for the S update (off-chain)
            float dto = __shfl_xor_sync(0xffffffffu, dt, 16);
            ull DA = pack2(lo16 ? dt  : dto);
            ull DB = pack2(lo16 ? dto : dt);

            // ---- off-chain: S update + o-dot + P_{t+3}-dot ----
            SA0 = ffma2(A.x, SA0, fmul2(K.x, DA));
            SA1 = ffma2(A.y, SA1, fmul2(K.y, DA));
            SB0 = ffma2(A.x, SB0, fmul2(K.x, DB));
            SB1 = ffma2(A.y, SB1, fmul2(K.y, DB));

            float oA = hsum2(ffma2(Q.x, SA0, fmul2(Q.y, SA1)));
            float oB = hsum2(ffma2(Q.x, SB0, fmul2(Q.y, SB1)));
            float pA = hsum2(ffma2(W.x, SA0, fmul2(W.y, SA1)));
            float pB = hsum2(ffma2(W.x, SB0, fmul2(W.y, SB1)));

            // ---- 4-value split-butterfly: 6 SHFL ----
            float t1 = lo16 ? pA : oA;
            float r1 = __shfl_xor_sync(0xffffffffu, t1, 16);
            float u  = (lo16 ? oA : pA) + r1;
            float t2 = lo16 ? pB : oB;
            float r2 = __shfl_xor_sync(0xffffffffu, t2, 16);
            float w2 = (lo16 ? oB : pB) + r2;
            float t3 = lo8 ? w2 : u;
            float r3 = __shfl_xor_sync(0xffffffffu, t3, 8);
            float v  = (lo8 ? u : w2) + r3;
            v += __shfl_xor_sync(0xffffffffu, v, 4);
            v += __shfl_xor_sync(0xffffffffu, v, 2);
            v += __shfl_xor_sync(0xffffffffu, v, 1);
            // v: lanes 0-7 = oA, 8-15 = oB, 16-23 = pA, 24-31 = pB

            // per-half P for step t+3 via one idx-shuffle
            Pq[(t + 3) & 3] = __shfl_sync(0xffffffffu, v, psrc);
            // predicated scalar store of o (lanes 0 and 8)
            if (do_store)
                sout[(size_t)t * (HH * DKK)] = v;
        }
        issue(g + 3);
    }
}

// --------------------------------------------------------------------------
extern "C" void kernel_launch(void* const* d_in, const int* in_sizes, int n_in,
                              void* d_out, int out_size) {
    const float* mixed_qkv   = (const float*)d_in[0];
    const float* forget_gate = (const float*)d_in[1];
    const float* beta        = (const float*)d_in[2];
    const float* conv_w      = (const float*)d_in[3];
    const float* A_log       = (const float*)d_in[4];
    const float* dt_bias     = (const float*)d_in[5];
    float* out = (float*)d_out;

    prep_kernel<<<(TT * HH) / 8, 256>>>(mixed_qkv, forget_gate, beta,
                                        conv_w, A_log, dt_bias);
    pass2_kernel<<<(TT * HH) / 8, 256>>>();
    recur_kernel<<<128, 256>>>(out);
}

// round 16
// speedup vs baseline: 1.9914x; 1.0578x over previous
#include <cuda_runtime.h>
#include <cuda_bf16.h>

// Problem constants
#define TT   4096
#define HH   16
#define DKK  128
#define QKVC 6144
#define NELEM (TT * HH * DKK)   // 8388608

// Scratch (static __device__ globals — no runtime allocation)
// g_P packed per (t,h): [slot0(128) | a(128) | k(128) | q(128)]
// slot0 holds ka after prep; pass2 overwrites it in place with
// w_t = ka_t ∘ a_{t-1} ∘ a_{t-2} (only warp (t,h) ever touches slot0 of (t,h)).
__device__ __align__(16) float g_P [TT * HH * 512];
__device__ __align__(16) float g_BV[NELEM];        // b * (conv+silu v)
__device__ __align__(16) float g_S4[TT * HH * 4];  // {b, R, Q, 0} per (t,h)
__device__ float g_B[TT * HH];                     // sigmoid(beta)

typedef unsigned long long ull;

// --------------------------------------------------------------------------
// f32x2 packed-math helpers (FFMA2 path; ptxas only emits via PTX f32x2)
// --------------------------------------------------------------------------
__device__ __forceinline__ ull ffma2(ull a, ull b, ull c) {
    ull d;
    asm("fma.rn.f32x2 %0, %1, %2, %3;" : "=l"(d) : "l"(a), "l"(b), "l"(c));
    return d;
}
__device__ __forceinline__ ull fmul2(ull a, ull b) {
    ull d;
    asm("mul.rn.f32x2 %0, %1, %2;" : "=l"(d) : "l"(a), "l"(b));
    return d;
}
__device__ __forceinline__ float hsum2(ull a) {
    float lo, hi;
    asm("mov.b64 {%0, %1}, %2;" : "=f"(lo), "=f"(hi) : "l"(a));
    return lo + hi;
}
__device__ __forceinline__ ull pack2(float x) {
    ull d;
    asm("mov.b64 %0, {%1, %1};" : "=l"(d) : "f"(x));
    return d;
}

// cp.async helper
__device__ __forceinline__ void cp16(float* dst, const float* src) {
    unsigned d = (unsigned)__cvta_generic_to_shared(dst);
    asm volatile("cp.async.cg.shared.global [%0], [%1], 16;"
                 :: "r"(d), "l"(src) : "memory");
}

// --------------------------------------------------------------------------
// Kernel 1: conv1d(K=4, depthwise, causal) + SiLU + l2norm + gate precompute.
// R16: one warp per (t-pair, h) — outputs t0 and t0+1. Shares 3 of 5 qkv
// rows and all 12 weight vectors between the two outputs (−35% L1 work).
// Segments (q,k,v) processed sequentially to bound the register window.
// --------------------------------------------------------------------------
__global__ void __launch_bounds__(256)
prep_kernel(const float* __restrict__ qkv,
            const float* __restrict__ fg,
            const float* __restrict__ beta,
            const float* __restrict__ w,
            const float* __restrict__ A_log,
            const float* __restrict__ dt_bias) {
    int gw   = (blockIdx.x * blockDim.x + threadIdx.x) >> 5;
    int lane = threadIdx.x & 31;
    if (gw >= TT * HH / 2) return;
    int t0 = (gw >> 4) << 1;     // even
    int h  = gw & 15;
    int d  = lane * 4;
    int cbase = h * DKK + d;

    // outputs: [step][seg*4+j]  (q: 0-3, k: 4-7, v: 8-11)
    float oy[2][12];
    const float4 z4 = make_float4(0.f, 0.f, 0.f, 0.f);

#pragma unroll
    for (int seg = 0; seg < 3; seg++) {
        const int c = cbase + seg * 2048;
        // depthwise weights for this segment's 4 channels
        float wz[4][4];
#pragma unroll
        for (int j = 0; j < 4; j++) {
            float4 wv = *(const float4*)(w + (size_t)(c + j) * 4);
            wz[j][0] = wv.x; wz[j][1] = wv.y; wz[j][2] = wv.z; wz[j][3] = wv.w;
        }
        // rows t0-3 .. t0+1 (5 rows, shared between the two outputs)
        float4 xr[5];
#pragma unroll
        for (int i = 0; i < 5; i++) {
            int r = t0 - 3 + i;
            xr[i] = (r >= 0) ? *(const float4*)(qkv + (size_t)r * QKVC + c)
                             : z4;
        }
#pragma unroll
        for (int s = 0; s < 2; s++) {
            float acc[4] = {0.f, 0.f, 0.f, 0.f};
#pragma unroll
            for (int tau = 0; tau < 4; tau++) {
                const float4 xv = xr[s + tau];
                acc[0] = fmaf(xv.x, wz[0][tau], acc[0]);
                acc[1] = fmaf(xv.y, wz[1][tau], acc[1]);
                acc[2] = fmaf(xv.z, wz[2][tau], acc[2]);
                acc[3] = fmaf(xv.w, wz[3][tau], acc[3]);
            }
#pragma unroll
            for (int j = 0; j < 4; j++)
                oy[s][seg * 4 + j] = acc[j] / (1.f + expf(-acc[j]));  // SiLU
        }
    }

    float  ea  = expf(A_log[h]);
    float4 dbv = *(const float4*)(dt_bias + h * DKK + d);

#pragma unroll
    for (int s = 0; s < 2; s++) {
        const int t = t0 + s;
        const float* qy = &oy[s][0];
        const float* ky = &oy[s][4];
        const float* vy = &oy[s][8];

        // l2norm sums
        float sq = 0.f, sk = 0.f;
#pragma unroll
        for (int j = 0; j < 4; j++) {
            sq = fmaf(qy[j], qy[j], sq);
            sk = fmaf(ky[j], ky[j], sk);
        }
#pragma unroll
        for (int m = 16; m > 0; m >>= 1) {
            sq += __shfl_xor_sync(0xffffffffu, sq, m);
            sk += __shfl_xor_sync(0xffffffffu, sk, m);
        }
        float se_q = sq + 1e-6f, se_k = sk + 1e-6f;
        float rq = rsqrtf(se_q); rq = rq * (1.5f - 0.5f * se_q * rq * rq);
        float rk = rsqrtf(se_k); rk = rk * (1.5f - 0.5f * se_k * rk * rk);
        rq *= 0.08838834764831845f;   // DK^-0.5

        // gate
        float4 fgv = *(const float4*)(fg + (size_t)t * (HH * DKK) + h * DKK + d);
        float zf[4] = {fgv.x + dbv.x, fgv.y + dbv.y, fgv.z + dbv.z, fgv.w + dbv.w};
        float bb = 1.f / (1.f + expf(-beta[t * HH + h]));

        float qn[4], kn[4], av[4], kav[4];
#pragma unroll
        for (int j = 0; j < 4; j++) {
            float z  = zf[j];
            float sp = (z > 20.f) ? z : log1pf(expf(z));   // softplus
            av[j]  = expf(-ea * sp);                       // a = exp(g)
            qn[j]  = qy[j] * rq;
            kn[j]  = ky[j] * rk;
            kav[j] = kn[j] * av[j];
        }

        size_t pb = ((size_t)t * HH + h) * 512 + d;
        *(float4*)(g_P + pb      ) = make_float4(kav[0], kav[1], kav[2], kav[3]);
        *(float4*)(g_P + pb + 128) = make_float4(av[0],  av[1],  av[2],  av[3]);
        *(float4*)(g_P + pb + 256) = make_float4(kn[0],  kn[1],  kn[2],  kn[3]);
        *(float4*)(g_P + pb + 384) = make_float4(qn[0],  qn[1],  qn[2],  qn[3]);
        *(float4*)(g_BV + ((size_t)t * HH + h) * DKK + d) =
            make_float4(vy[0] * bb, vy[1] * bb, vy[2] * bb, vy[3] * bb);
        if (lane == 0)
            g_B[t * HH + h] = bb;
    }
}

// --------------------------------------------------------------------------
// Kernel 1b: lookahead precompute. One warp per (t,h).
//   w_t = ka_t ∘ a_{t-1} ∘ a_{t-2}      (overwrite slot0 in place)
//   R_t = (ka_t ∘ a_{t-1}) · k_{t-2}    (scalar)
//   Q_t = ka_t · k_{t-1}                (scalar)
// Negative t indices: a := 1, k := 0.
// --------------------------------------------------------------------------
__global__ void pass2_kernel() {
    int gw   = (blockIdx.x * blockDim.x + threadIdx.x) >> 5;
    int lane = threadIdx.x & 31;
    if (gw >= TT * HH) return;
    int t = gw >> 4;
    int h = gw & 15;
    int d = lane * 4;

    size_t bt = ((size_t)t * HH + h) * 512;
    const size_t ts = (size_t)HH * 512;

    float4 ka = *(const float4*)(g_P + bt + d);
    float4 a1 = make_float4(1.f, 1.f, 1.f, 1.f);
    float4 a2 = make_float4(1.f, 1.f, 1.f, 1.f);
    float4 k1 = make_float4(0.f, 0.f, 0.f, 0.f);
    float4 k2 = make_float4(0.f, 0.f, 0.f, 0.f);
    if (t >= 1) {
        a1 = *(const float4*)(g_P + bt - ts + 128 + d);
        k1 = *(const float4*)(g_P + bt - ts + 256 + d);
    }
    if (t >= 2) {
        a2 = *(const float4*)(g_P + bt - 2 * ts + 128 + d);
        k2 = *(const float4*)(g_P + bt - 2 * ts + 256 + d);
    }
    float4 u = make_float4(ka.x * a1.x, ka.y * a1.y, ka.z * a1.z, ka.w * a1.w);
    float4 wv = make_float4(u.x * a2.x, u.y * a2.y, u.z * a2.z, u.w * a2.w);

    float rp = fmaf(u.x, k2.x, u.y * k2.y) + fmaf(u.z, k2.z, u.w * k2.w);
    float qp = fmaf(ka.x, k1.x, ka.y * k1.y) + fmaf(ka.z, k1.z, ka.w * k1.w);
#pragma unroll
    for (int m = 16; m > 0; m >>= 1) {
        rp += __shfl_xor_sync(0xffffffffu, rp, m);
        qp += __shfl_xor_sync(0xffffffffu, qp, m);
    }
    *(float4*)(g_P + bt + d) = wv;            // slot0 := w (safe: private)
    if (lane == 0)
        *(float4*)(g_S4 + ((size_t)t * HH + h) * 4) =
            make_float4(g_B[t * HH + h], rp, qp, 0.f);
}

// --------------------------------------------------------------------------
// Kernel 2: gated delta-rule recurrence with 3-step lookahead.
// CTA = 256 threads (8 warps) = 16 v-columns; one warp = 2 v-columns.
// Lane owns k-quad 4*lane..4*lane+3 (distinct-per-lane LDS.128).
// Scalar HALF-LANE chain (lanes 0-15 col A, 16-31 col B);
// 4-value split-butterfly reduction (6 SHFL).  (identical to R15)
// --------------------------------------------------------------------------
#define STGF 544   // floats per stage: 512 packed + 16 bv + 4 scalars + pad
#define NST  16    // 4 groups x 4 steps in-flight ring

__global__ void __launch_bounds__(256, 1)
recur_kernel(float* __restrict__ out) {
    __shared__ __align__(16) float sm[NST * STGF];

    const int tid  = threadIdx.x;
    const int warp = tid >> 5;
    const int lane = tid & 31;
    const int h    = blockIdx.x >> 3;
    const int vb   = (blockIdx.x & 7) * 16;       // CTA's 16-column slab
    float* outp = out + h * DKK + vb + warp * 2;

    auto issue = [&](int g) {
#pragma unroll
        for (int s = 0; s < 4; s++) {
            int tu = 4 * g + s;
            float* sp = sm + (tu & 15) * STGF;
            int t = (tu > TT - 1) ? (TT - 1) : tu;
            const float* gp = g_P + ((size_t)t * HH + h) * 512;
            if (tid < 128) cp16(sp + tid * 4, gp + tid * 4);
            if (tid >= 128 && tid < 132)
                cp16(sp + 512 + (tid - 128) * 4,
                     g_BV + ((size_t)t * HH + h) * DKK + vb + (tid - 128) * 4);
            if (tid == 132)
                cp16(sp + 528, g_S4 + ((size_t)t * HH + h) * 4);
        }
        asm volatile("cp.async.commit_group;" ::: "memory");
    };

    issue(0); issue(1); issue(2);

    ull SA0 = 0, SA1 = 0, SB0 = 0, SB1 = 0;
    float Pq[4] = {0.f, 0.f, 0.f, 0.f};   // per-half reduced P, steps t..t+3
    float d1 = 0.f, d2 = 0.f;             // per-half delta_{t-1}, delta_{t-2}
    const bool lo16 = (lane < 16);
    const bool lo8  = ((lane & 8) == 0);
    // shfl.idx source: lanes 0-15 fetch pA (lanes 16-23), 16-31 fetch pB (24-31)
    const int  psrc = 16 | ((lane & 16) >> 1) | (lane & 7);
    // per-half bv smem offset: col A for lanes 0-15, col B for lanes 16-31
    const int  bvix = 512 + warp * 2 + (lane >> 4);
    // predicated scalar store: lane 0 -> col A, lane 8 -> col B
    float* sout = outp + ((lane >> 3) & 1);
    const bool do_store = (lane == 0) || (lane == 8);

    for (int g = 0; g < TT / 4; g++) {
        // groups g and g+1 complete (w of t+3 lives in group g+1)
        asm volatile("cp.async.wait_group 1;" ::: "memory");
        __syncthreads();
#pragma unroll
        for (int s = 0; s < 4; s++) {
            const int t = 4 * g + s;
            const float* spb = sm + (t & 15) * STGF;
            const float* spn = sm + ((t + 3) & 15) * STGF;  // w_{t+3}
            const int lo = lane * 4;

            // distinct-per-lane array loads (one LDS.128 per array)
            ulonglong2 A = *(const ulonglong2*)(spb + 128 + lo);
            ulonglong2 K = *(const ulonglong2*)(spb + 256 + lo);
            ulonglong2 Q = *(const ulonglong2*)(spb + 384 + lo);
            ulonglong2 W = *(const ulonglong2*)(spn + lo);

            float4 s4 = *(const float4*)(spb + 528);    // {b, R, Q, -}
            float  bv = spb[bvix];                      // per-half column bv

            // ---- critical chain: 3 dependent scalar FFMAs (per half) ----
            float r  = fmaf(d2, s4.y, Pq[t & 3]);
            r        = fmaf(d1, s4.z, r);
            float dt = fmaf(-s4.x, r, bv);
            d2 = d1; d1 = dt;

            // exchange dt across halves for the S update (off-chain)
            float dto = __shfl_xor_sync(0xffffffffu, dt, 16);
            ull DA = pack2(lo16 ? dt  : dto);
            ull DB = pack2(lo16 ? dto : dt);

            // ---- off-chain: S update + o-dot + P_{t+3}-dot ----
            SA0 = ffma2(A.x, SA0, fmul2(K.x, DA));
            SA1 = ffma2(A.y, SA1, fmul2(K.y, DA));
            SB0 = ffma2(A.x, SB0, fmul2(K.x, DB));
            SB1 = ffma2(A.y, SB1, fmul2(K.y, DB));

            float oA = hsum2(ffma2(Q.x, SA0, fmul2(Q.y, SA1)));
            float oB = hsum2(ffma2(Q.x, SB0, fmul2(Q.y, SB1)));
            float pA = hsum2(ffma2(W.x, SA0, fmul2(W.y, SA1)));
            float pB = hsum2(ffma2(W.x, SB0, fmul2(W.y, SB1)));

            // ---- 4-value split-butterfly: 6 SHFL ----
            float t1 = lo16 ? pA : oA;
            float r1 = __shfl_xor_sync(0xffffffffu, t1, 16);
            float u  = (lo16 ? oA : pA) + r1;
            float t2 = lo16 ? pB : oB;
            float r2 = __shfl_xor_sync(0xffffffffu, t2, 16);
            float w2 = (lo16 ? oB : pB) + r2;
            float t3 = lo8 ? w2 : u;
            float r3 = __shfl_xor_sync(0xffffffffu, t3, 8);
            float v  = (lo8 ? u : w2) + r3;
            v += __shfl_xor_sync(0xffffffffu, v, 4);
            v += __shfl_xor_sync(0xffffffffu, v, 2);
            v += __shfl_xor_sync(0xffffffffu, v, 1);
            // v: lanes 0-7 = oA, 8-15 = oB, 16-23 = pA, 24-31 = pB

            // per-half P for step t+3 via one idx-shuffle
            Pq[(t + 3) & 3] = __shfl_sync(0xffffffffu, v, psrc);
            // predicated scalar store of o (lanes 0 and 8)
            if (do_store)
                sout[(size_t)t * (HH * DKK)] = v;
        }
        issue(g + 3);
    }
}

// --------------------------------------------------------------------------
extern "C" void kernel_launch(void* const* d_in, const int* in_sizes, int n_in,
                              void* d_out, int out_size) {
    const float* mixed_qkv   = (const float*)d_in[0];
    const float* forget_gate = (const float*)d_in[1];
    const float* beta        = (const float*)d_in[2];
    const float* conv_w      = (const float*)d_in[3];
    const float* A_log       = (const float*)d_in[4];
    const float* dt_bias     = (const float*)d_in[5];
    float* out = (float*)d_out;

    // 32768 (t-pair, h) warps, 8 per 256-thread block
    prep_kernel<<<(TT * HH / 2) / 8, 256>>>(mixed_qkv, forget_gate, beta,
                                            conv_w, A_log, dt_bias);
    pass2_kernel<<<(TT * HH) / 8, 256>>>();
    recur_kernel<<<128, 256>>>(out);
}